// round 2
// baseline (speedup 1.0000x reference)
#include <cuda_runtime.h>

// HarmonicLowering: out[b, k*C+ch, f, t] = w * x[b,ch,idx,t] + (1-w) * x[b,ch,idx1,t]
//   prod = f*(k+1); idx = prod/4; frac = (prod%4)*0.25; w = 1-frac; idx1 = min(idx+1, F-1)
// B=8, C=32, F=256, T=512, K=4. All powers of two -> shift/mask index decode.

#define BATCH 8
#define CH    32
#define FREQ  256
#define TIME  512
#define KTAPS 4

#define T4       (TIME / 4)                          // 128 float4 per time-row
#define OUT_E4   (BATCH * KTAPS * CH * FREQ * T4)    // 33,554,432

__global__ __launch_bounds__(256, 8)
void harmonic_lowering_kernel(const float4* __restrict__ x, float4* __restrict__ out)
{
    unsigned int i = blockIdx.x * blockDim.x + threadIdx.x;
    if (i >= OUT_E4) return;

    // decode: i = (((b*128 + kc)*256 + f)*128 + t4)
    unsigned int t4 = i & (T4 - 1);            // bits [0:7)
    unsigned int f  = (i >> 7) & (FREQ - 1);   // bits [7:15)
    unsigned int kc = (i >> 15) & 127;         // bits [15:22)  k*32 + ch
    unsigned int b  = i >> 22;                 // bits [22:25)

    unsigned int k  = kc >> 5;                 // 0..3, tap = k+1
    unsigned int ch = kc & 31;

    unsigned int prod = f * (k + 1);
    unsigned int idx  = prod >> 2;
    unsigned int idx1 = idx + 1;
    if (idx1 > FREQ - 1) idx1 = FREQ - 1;
    float w = 1.0f - (float)(prod & 3) * 0.25f;

    // input offset (float4 units): ((b*CH + ch)*FREQ + row)*T4 + t4
    unsigned int base = ((b * CH + ch) * FREQ) * T4 + t4;
    float4 g0 = x[base + idx  * T4];
    float4 g1 = x[base + idx1 * T4];

    float4 r;
    r.x = fmaf(w, g0.x - g1.x, g1.x);
    r.y = fmaf(w, g0.y - g1.y, g1.y);
    r.z = fmaf(w, g0.z - g1.z, g1.z);
    r.w = fmaf(w, g0.w - g1.w, g1.w);

    out[i] = r;
}

extern "C" void kernel_launch(void* const* d_in, const int* in_sizes, int n_in,
                              void* d_out, int out_size)
{
    (void)in_sizes; (void)n_in; (void)out_size;
    const float4* x = (const float4*)d_in[0];
    float4* out = (float4*)d_out;

    const int threads = 256;
    const int blocks  = (OUT_E4 + threads - 1) / threads;   // 131072, exact
    harmonic_lowering_kernel<<<blocks, threads>>>(x, out);
}

// round 3
// speedup vs baseline: 1.0930x; 1.0930x over previous
#include <cuda_runtime.h>

// HarmonicLowering: out[b, k*C+ch, f, t] = w * x[b,ch,idx,t] + (1-w) * x[b,ch,idx1,t]
//   prod = f*(k+1); idx = prod>>2; w = 1 - (prod&3)*0.25
//   Note: w<1 implies idx<=191, so idx+1 never needs clamping; when w==1 the
//   result is g0 regardless of g1, so we alias idx1=idx (same-address L1 hit).
// B=8, C=32, F=256, T=512, K=4. All powers of two -> shift/mask decode.

#define BATCH 8
#define CH    32
#define FREQ  256
#define TIME  512
#define KTAPS 4

#define T4       (TIME / 4)                          // 128 float4 per time-row
#define OUT_E4   (BATCH * KTAPS * CH * FREQ * T4)    // 33,554,432

__global__ __launch_bounds__(256)
void harmonic_lowering_kernel(const float4* __restrict__ x, float4* __restrict__ out)
{
    const unsigned int i0 = blockIdx.x * 512u + threadIdx.x;
    const unsigned int i1 = i0 + 256u;

    // ---- decode element A ----
    unsigned int t4a = i0 & (T4 - 1);
    unsigned int fa  = (i0 >> 7) & (FREQ - 1);
    unsigned int kca = (i0 >> 15) & 127u;
    unsigned int ba  = i0 >> 22;
    unsigned int proda = fa * ((kca >> 5) + 1u);
    unsigned int fraca = proda & 3u;
    unsigned int idxa  = proda >> 2;
    unsigned int idx1a = fraca ? (idxa + 1u) : idxa;
    float wa = 1.0f - (float)fraca * 0.25f;
    unsigned int basea = ((ba * CH + (kca & 31u)) * FREQ) * T4 + t4a;

    // ---- decode element B ----
    unsigned int t4b = i1 & (T4 - 1);
    unsigned int fb  = (i1 >> 7) & (FREQ - 1);
    unsigned int kcb = (i1 >> 15) & 127u;
    unsigned int bb  = i1 >> 22;
    unsigned int prodb = fb * ((kcb >> 5) + 1u);
    unsigned int fracb = prodb & 3u;
    unsigned int idxb  = prodb >> 2;
    unsigned int idx1b = fracb ? (idxb + 1u) : idxb;
    float wb = 1.0f - (float)fracb * 0.25f;
    unsigned int baseb = ((bb * CH + (kcb & 31u)) * FREQ) * T4 + t4b;

    // ---- front-batched loads (4 independent LDG.128) ----
    float4 g0a = x[basea + idxa  * T4];
    float4 g1a = x[basea + idx1a * T4];
    float4 g0b = x[baseb + idxb  * T4];
    float4 g1b = x[baseb + idx1b * T4];

    // ---- lerp ----
    float4 ra, rb;
    ra.x = fmaf(wa, g0a.x - g1a.x, g1a.x);
    ra.y = fmaf(wa, g0a.y - g1a.y, g1a.y);
    ra.z = fmaf(wa, g0a.z - g1a.z, g1a.z);
    ra.w = fmaf(wa, g0a.w - g1a.w, g1a.w);
    rb.x = fmaf(wb, g0b.x - g1b.x, g1b.x);
    rb.y = fmaf(wb, g0b.y - g1b.y, g1b.y);
    rb.z = fmaf(wb, g0b.z - g1b.z, g1b.z);
    rb.w = fmaf(wb, g0b.w - g1b.w, g1b.w);

    // ---- streaming stores (evict-first: keep L2 for the reused input) ----
    __stcs(&out[i0], ra);
    __stcs(&out[i1], rb);
}

extern "C" void kernel_launch(void* const* d_in, const int* in_sizes, int n_in,
                              void* d_out, int out_size)
{
    (void)in_sizes; (void)n_in; (void)out_size;
    const float4* x = (const float4*)d_in[0];
    float4* out = (float4*)d_out;

    const int threads = 256;
    const int blocks  = OUT_E4 / (threads * 2);   // 65536, exact
    harmonic_lowering_kernel<<<blocks, threads>>>(x, out);
}